// round 1
// baseline (speedup 1.0000x reference)
#include <cuda_runtime.h>
#include <cub/block/block_radix_sort.cuh>

// LongRankIC: per column c of 4096, top-k (k=4096) of preds[:,c] (N=8192),
// Spearman of within-subset ranks of (pred, target).
// Ranks are permutations of 0..k-1 -> ic = (S/k - mu^2) / (k(k+1)/12 + eps),
// S = sum p_rank*t_rank (exact integer).

#define NROWS 8192
#define NCOLS 4096
#define KSEL  4096
#define BT    1024
#define IPT1  8   // items/thread, first sort (8192 elements)
#define IPT2  4   // items/thread, second sort (4096 elements)

using Sort1 = cub::BlockRadixSort<unsigned, BT, IPT1, unsigned>;
using Sort2 = cub::BlockRadixSort<unsigned, BT, IPT2, unsigned>;

// order-preserving float -> uint mapping (no NaNs in input)
__device__ __forceinline__ unsigned f2u(float f) {
    unsigned u = __float_as_uint(f);
    return u ^ ((unsigned)((int)u >> 31) | 0x80000000u);
}

__global__ void __launch_bounds__(BT, 1)
rank_ic_kernel(const float* __restrict__ preds,
               const float* __restrict__ targets,
               float* __restrict__ out)
{
    __shared__ union {
        typename Sort1::TempStorage s1;
        typename Sort2::TempStorage s2;
    } ts;
    extern __shared__ char dyn[];
    float*    tcol = (float*)dyn;                    // NROWS floats (32 KB)
    unsigned* skey = (unsigned*)(dyn + NROWS * 4);   // KSEL u32
    unsigned* sval = skey + KSEL;                    // KSEL u32

    const int c = blockIdx.x;
    const int t = threadIdx.x;

    // ---- load pred column into registers (keys) + target column into smem ----
    unsigned keys[IPT1], vals[IPT1];
#pragma unroll
    for (int j = 0; j < IPT1; j++) {
        int r = t * IPT1 + j;
        keys[j] = f2u(__ldg(preds + (size_t)r * NCOLS + c));
        vals[j] = (unsigned)r;
    }
    for (int i = t; i < NROWS; i += BT)
        tcol[i] = __ldg(targets + (size_t)i * NCOLS + c);
    __syncthreads();

    // ---- sort 1: ascending by pred key, payload = original row ----
    Sort1(ts.s1).Sort(keys, vals);
    // blocked output: thread t item j sits at global ascending rank r = t*IPT1+j.
    // selected subset = ranks [KSEL, 2*KSEL); p_rank = r - KSEL.
#pragma unroll
    for (int j = 0; j < IPT1; j++) {
        int r = t * IPT1 + j;
        if (r >= KSEL) {
            skey[r - KSEL] = f2u(tcol[vals[j]]);
            sval[r - KSEL] = (unsigned)(r - KSEL);   // p_rank
        }
    }
    __syncthreads();

    // ---- sort 2: ascending by target key, payload = p_rank ----
    unsigned k2[IPT2], v2[IPT2];
#pragma unroll
    for (int j = 0; j < IPT2; j++) {
        k2[j] = skey[t * IPT2 + j];
        v2[j] = sval[t * IPT2 + j];
    }
    __syncthreads();
    Sort2(ts.s2).Sort(k2, v2);
    // position t*IPT2+j = t_rank; payload = p_rank.

    unsigned long long s = 0;
#pragma unroll
    for (int j = 0; j < IPT2; j++)
        s += (unsigned long long)(unsigned)(t * IPT2 + j) * (unsigned long long)v2[j];

    // ---- block reduction of S (reuse dynamic smem) ----
    __syncthreads();
    unsigned long long* red = (unsigned long long*)dyn;
    red[t] = s;
    __syncthreads();
#pragma unroll
    for (int off = BT / 2; off > 0; off >>= 1) {
        if (t < off) red[t] += red[t + off];
        __syncthreads();
    }

    if (t == 0) {
        double S   = (double)red[0];
        double k   = (double)KSEL;
        double mu  = (k - 1.0) * 0.5;
        double cov = S / k - mu * mu;
        double var = k * (k + 1.0) / 12.0;   // ddof=1 variance of 0..k-1
        out[c] = (float)(cov / (var + 1e-8));
    }
}

extern "C" void kernel_launch(void* const* d_in, const int* in_sizes, int n_in,
                              void* d_out, int out_size)
{
    const float* preds   = (const float*)d_in[0];
    const float* targets = (const float*)d_in[1];
    float*       out     = (float*)d_out;

    const int dyn = NROWS * 4 + KSEL * 8;  // 64 KB dynamic smem
    cudaFuncSetAttribute(rank_ic_kernel,
                         cudaFuncAttributeMaxDynamicSharedMemorySize, dyn);
    rank_ic_kernel<<<NCOLS, BT, dyn>>>(preds, targets, out);
}

// round 5
// speedup vs baseline: 2.1474x; 2.1474x over previous
#include <cuda_runtime.h>

// LongRankIC via exact binned ranking (no sort).
// ic = (S/k - mu^2)/(k(k+1)/12 + eps), S = sum over selected of p_rank*t_rank,
// ranks are permutations of 0..k-1. Selection = ascending pred-rank in [k,2k).
//
// Pipeline:
//  K1: tiled transpose preds/targets -> column-major static scratch (coalesced).
//  K2: one CTA per column:
//    phase 1: bin pred values (monotone linear bins), hist+scan+scatter,
//             exact rank = bin_base + #smaller-in-bin (packed u64 compare).
//             selected (rank>=k) -> t2[p_rank] = (t_key<<13 | p_rank).
//    phase 2: same binned ranking on the 4096 selected target keys,
//             accumulate S = sum p_rank * t_rank.

#define NR 8192
#define NC 4096
#define KSEL 4096
#define BT 1024
#define NB 4096
#define IPT 8
#define IPT2 4

__device__ float g_pT[(size_t)NC * NR];  // preds transposed  [col][row]
__device__ float g_tT[(size_t)NC * NR];  // targets transposed

__device__ __forceinline__ unsigned f2u(float f) {
    unsigned u = __float_as_uint(f);
    return u ^ ((unsigned)((int)u >> 31) | 0x80000000u);
}
__device__ __forceinline__ float u2f(unsigned u) {
    unsigned v = (u & 0x80000000u) ? (u ^ 0x80000000u) : ~u;
    return __uint_as_float(v);
}
// exactly monotone (non-strict) in x; balance tuned for N(0,1)
__device__ __forceinline__ int binf(float x) {
    int b = (int)fmaf(x, 512.0f, 2048.0f);
    return min(max(b, 0), NB - 1);
}

// ---------------- transpose ----------------
__global__ void transpose_k(const float* __restrict__ preds,
                            const float* __restrict__ targets)
{
    __shared__ float tile[32][33];
    const float* src = blockIdx.z ? targets : preds;
    float* dst       = blockIdx.z ? g_tT : g_pT;
    int c0 = blockIdx.x * 32, r0 = blockIdx.y * 32;
    int tx = threadIdx.x, ty = threadIdx.y;
#pragma unroll
    for (int i = ty; i < 32; i += 8)
        tile[i][tx] = src[(size_t)(r0 + i) * NC + c0 + tx];
    __syncthreads();
#pragma unroll
    for (int i = ty; i < 32; i += 8)
        dst[(size_t)(c0 + i) * NR + r0 + tx] = tile[tx][i];
}

// ---------------- smem layout for main kernel ----------------
#define G_OFF    0                     // u64[NR]    65536 B (also reused for phase-2 scatter dest)
#define TCOL_OFF 65536                 // f32[NR]    32768
#define T2_OFF   98304                 // u64[KSEL]  32768
#define HIST_OFF 131072                // u32[NB]    16384
#define CUR_OFF  147456                // u32[NB]    16384
#define B2_OFF   163840                // u16[KSEL]   8192
#define WSCR_OFF 172032                // u32[32]      128
#define RED_OFF  172160                // u64[32]      256
#define SMEM_TOTAL 172416

// exclusive scan of hist[0..NB) -> cur[0..NB), all BT threads participate
__device__ __forceinline__ void scan_bins(unsigned* hist, unsigned* cur,
                                          unsigned* wscr, int t)
{
    unsigned v0 = hist[4*t], v1 = hist[4*t+1], v2 = hist[4*t+2], v3 = hist[4*t+3];
    unsigned s01 = v0 + v1;
    unsigned s = s01 + v2 + v3;
    unsigned inc = s;
#pragma unroll
    for (int d = 1; d < 32; d <<= 1) {
        unsigned n = __shfl_up_sync(0xffffffffu, inc, d);
        if ((t & 31) >= d) inc += n;
    }
    if ((t & 31) == 31) wscr[t >> 5] = inc;
    __syncthreads();
    if (t < 32) {
        unsigned w = wscr[t];
        unsigned wi = w;
#pragma unroll
        for (int d = 1; d < 32; d <<= 1) {
            unsigned n = __shfl_up_sync(0xffffffffu, wi, d);
            if (t >= d) wi += n;
        }
        wscr[t] = wi - w;  // exclusive across warps
    }
    __syncthreads();
    unsigned base = wscr[t >> 5] + (inc - s);  // exclusive prefix of this thread's chunk
    cur[4*t]   = base;
    cur[4*t+1] = base + v0;
    cur[4*t+2] = base + s01;
    cur[4*t+3] = base + s01 + v2;
}

__global__ void __launch_bounds__(BT, 1)
rank_ic_kernel(float* __restrict__ out)
{
    extern __shared__ char sm[];
    unsigned long long* g    = (unsigned long long*)(sm + G_OFF);
    float*              tcol = (float*)(sm + TCOL_OFF);
    unsigned long long* t2   = (unsigned long long*)(sm + T2_OFF);
    unsigned*           hist = (unsigned*)(sm + HIST_OFF);
    unsigned*           cur  = (unsigned*)(sm + CUR_OFF);
    unsigned short*     b2   = (unsigned short*)(sm + B2_OFF);
    unsigned*           wscr = (unsigned*)(sm + WSCR_OFF);
    unsigned long long* red  = (unsigned long long*)(sm + RED_OFF);

    const int c = blockIdx.x;
    const int t = threadIdx.x;
    const float* __restrict__ pcol = g_pT + (size_t)c * NR;
    const float* __restrict__ tccc = g_tT + (size_t)c * NR;

    // ---- zero hist, load columns (coalesced: cyclic rows) ----
    for (int i = t; i < NB; i += BT) hist[i] = 0;
    float pv[IPT];
#pragma unroll
    for (int j = 0; j < IPT; j++) {
        pv[j] = pcol[t + j * BT];
        tcol[t + j * BT] = tccc[t + j * BT];
    }
    __syncthreads();

    // ---- phase 1: histogram pred bins ----
    unsigned long long rec[IPT];
    int bn[IPT];
#pragma unroll
    for (int j = 0; j < IPT; j++) {
        unsigned row = (unsigned)(t + j * BT);
        unsigned key = f2u(pv[j]);
        bn[j]  = binf(pv[j]);
        rec[j] = ((unsigned long long)key << 13) | row;
        atomicAdd(&hist[bn[j]], 1u);
    }
    __syncthreads();
    scan_bins(hist, cur, wscr, t);
    __syncthreads();
#pragma unroll
    for (int j = 0; j < IPT; j++) {
        unsigned s = atomicAdd(&cur[bn[j]], 1u);
        g[s] = rec[j];
    }
    __syncthreads();
    // now cur[b] = end of group b, hist[b] = count; group = [end-cnt, end)

    // ---- phase 1 rank + select (process slots in grouped order: warp-coherent) ----
#pragma unroll
    for (int j = 0; j < IPT; j++) {
        int s = t * IPT + j;
        unsigned long long r = g[s];
        unsigned key = (unsigned)(r >> 13);
        int b = binf(u2f(key));
        unsigned end = cur[b], cnt = hist[b], start = end - cnt;
        unsigned rk = start;
        for (unsigned q = start; q < end; q++)
            rk += (g[q] < r);
        if (rk >= KSEL) {
            unsigned pr  = rk - KSEL;           // p_rank
            unsigned row = (unsigned)(r & 8191u);
            float tv = tcol[row];
            t2[pr] = ((unsigned long long)f2u(tv) << 13) | pr;
            b2[pr] = (unsigned short)binf(tv);
        }
    }
    __syncthreads();

    // ---- phase 2: histogram target bins of selected ----
    for (int i = t; i < NB; i += BT) hist[i] = 0;
    __syncthreads();
    int bn2[IPT2];
#pragma unroll
    for (int j = 0; j < IPT2; j++) {
        bn2[j] = b2[t + j * BT];
        atomicAdd(&hist[bn2[j]], 1u);
    }
    __syncthreads();
    scan_bins(hist, cur, wscr, t);
    __syncthreads();
#pragma unroll
    for (int j = 0; j < IPT2; j++) {
        unsigned long long r = t2[t + j * BT];
        unsigned s = atomicAdd(&cur[bn2[j]], 1u);
        g[s] = r;
    }
    __syncthreads();

    // ---- phase 2 rank + dot product ----
    unsigned long long acc = 0;
#pragma unroll
    for (int j = 0; j < IPT2; j++) {
        int s = t * IPT2 + j;
        unsigned long long r = g[s];
        unsigned key = (unsigned)(r >> 13);
        int b = binf(u2f(key));
        unsigned end = cur[b], cnt = hist[b], start = end - cnt;
        unsigned rk = start;                    // t_rank
        for (unsigned q = start; q < end; q++)
            rk += (g[q] < r);
        acc += (unsigned long long)(r & 8191u) * (unsigned long long)rk;
    }

    // ---- reduce S ----
#pragma unroll
    for (int d = 16; d > 0; d >>= 1)
        acc += __shfl_down_sync(0xffffffffu, acc, d);
    if ((t & 31) == 0) red[t >> 5] = acc;
    __syncthreads();
    if (t < 32) {
        unsigned long long v = red[t];
#pragma unroll
        for (int d = 16; d > 0; d >>= 1)
            v += __shfl_down_sync(0xffffffffu, v, d);
        if (t == 0) {
            double S   = (double)v;
            double k   = (double)KSEL;
            double mu  = (k - 1.0) * 0.5;
            double cov = S / k - mu * mu;
            double var = k * (k + 1.0) / 12.0;
            out[c] = (float)(cov / (var + 1e-8));
        }
    }
}

extern "C" void kernel_launch(void* const* d_in, const int* in_sizes, int n_in,
                              void* d_out, int out_size)
{
    const float* preds   = (const float*)d_in[0];
    const float* targets = (const float*)d_in[1];
    float*       out     = (float*)d_out;

    dim3 tb(32, 8, 1);
    dim3 tg(NC / 32, NR / 32, 2);
    transpose_k<<<tg, tb>>>(preds, targets);

    cudaFuncSetAttribute(rank_ic_kernel,
                         cudaFuncAttributeMaxDynamicSharedMemorySize, SMEM_TOTAL);
    rank_ic_kernel<<<NC, BT, SMEM_TOTAL>>>(out);
}

// round 6
// speedup vs baseline: 2.7403x; 1.2761x over previous
#include <cuda_runtime.h>

// LongRankIC via exact binned ranking (no sort).
// ic = (S/k - mu^2)/(k(k+1)/12 + eps), S = sum over selected of p_rank*t_rank.
// Selection = ascending pred-rank in [k,2k). Ranks exact via 8192-bin
// histogram + within-bin count of strictly-smaller packed (key,row) u64s.

#define NR 8192
#define NC 4096
#define KSEL 4096
#define BT 1024
#define NB 8192
#define IPT 8
#define IPT2 4

__device__ float g_pT[(size_t)NC * NR];
__device__ float g_tT[(size_t)NC * NR];

__device__ __forceinline__ unsigned f2u(float f) {
    unsigned u = __float_as_uint(f);
    return u ^ ((unsigned)((int)u >> 31) | 0x80000000u);
}
__device__ __forceinline__ float u2f(unsigned u) {
    unsigned v = (u & 0x80000000u) ? (u ^ 0x80000000u) : ~u;
    return __uint_as_float(v);
}
// monotone (non-strict) in x; NB bins over ~[-4,4)
__device__ __forceinline__ int binf(float x) {
    int b = (int)fmaf(x, 1024.0f, 4096.0f);
    return min(max(b, 0), NB - 1);
}

// ---------------- transpose: 64x64 tiles, float4 ----------------
__global__ void transpose_k(const float* __restrict__ preds,
                            const float* __restrict__ targets)
{
    __shared__ float tile[64][65];
    const float* src = blockIdx.z ? targets : preds;
    float* dst       = blockIdx.z ? g_tT : g_pT;
    int c0 = blockIdx.x * 64, r0 = blockIdx.y * 64;
    int tx = threadIdx.x, ty = threadIdx.y;   // (16,16)
#pragma unroll
    for (int k = 0; k < 4; k++) {
        int row = r0 + ty + 16 * k;
        float4 f = *(const float4*)&src[(size_t)row * NC + c0 + 4 * tx];
        tile[ty + 16 * k][4 * tx + 0] = f.x;
        tile[ty + 16 * k][4 * tx + 1] = f.y;
        tile[ty + 16 * k][4 * tx + 2] = f.z;
        tile[ty + 16 * k][4 * tx + 3] = f.w;
    }
    __syncthreads();
#pragma unroll
    for (int k = 0; k < 4; k++) {
        int j = ty + 16 * k;                  // column index within tile
        float4 o;
        o.x = tile[4 * tx + 0][j];
        o.y = tile[4 * tx + 1][j];
        o.z = tile[4 * tx + 2][j];
        o.w = tile[4 * tx + 3][j];
        *(float4*)&dst[(size_t)(c0 + j) * NR + r0 + 4 * tx] = o;
    }
}

// ---------------- smem layout ----------------
#define G_OFF    0          // u64[NR]   65536
#define TCOL_OFF 65536      // f32[NR]   32768
#define T2_OFF   98304      // u64[KSEL] 32768
#define HIST_OFF 131072     // u32[NB]   32768  (packed start<<16|end after scatter)
#define CUR_OFF  163840     // u32[NB]   32768
#define WSCR_OFF 196608     // u32[32]   128
#define RED_OFF  196736     // u64[32]   256
#define SMEM_TOTAL 196992

// exclusive scan of hist[0..NB) -> cur[0..NB); 8 bins/thread
__device__ __forceinline__ void scan_bins8(unsigned* hist, unsigned* cur,
                                           unsigned* wscr, int t)
{
    uint4 a = *(uint4*)&hist[8 * t];
    uint4 b = *(uint4*)&hist[8 * t + 4];
    unsigned pre[8];
    unsigned e = 0;
    pre[0] = e; e += a.x; pre[1] = e; e += a.y;
    pre[2] = e; e += a.z; pre[3] = e; e += a.w;
    pre[4] = e; e += b.x; pre[5] = e; e += b.y;
    pre[6] = e; e += b.z; pre[7] = e; e += b.w;
    unsigned inc = e;
#pragma unroll
    for (int d = 1; d < 32; d <<= 1) {
        unsigned n = __shfl_up_sync(0xffffffffu, inc, d);
        if ((t & 31) >= d) inc += n;
    }
    if ((t & 31) == 31) wscr[t >> 5] = inc;
    __syncthreads();
    if (t < 32) {
        unsigned w = wscr[t];
        unsigned wi = w;
#pragma unroll
        for (int d = 1; d < 32; d <<= 1) {
            unsigned n = __shfl_up_sync(0xffffffffu, wi, d);
            if (t >= d) wi += n;
        }
        wscr[t] = wi - w;
    }
    __syncthreads();
    unsigned base = wscr[t >> 5] + (inc - e);
    uint4 o0 = make_uint4(base + pre[0], base + pre[1], base + pre[2], base + pre[3]);
    uint4 o1 = make_uint4(base + pre[4], base + pre[5], base + pre[6], base + pre[7]);
    *(uint4*)&cur[8 * t]     = o0;
    *(uint4*)&cur[8 * t + 4] = o1;
}

__global__ void __launch_bounds__(BT, 1)
rank_ic_kernel(float* __restrict__ out)
{
    extern __shared__ char sm[];
    unsigned long long* g    = (unsigned long long*)(sm + G_OFF);
    float*              tcol = (float*)(sm + TCOL_OFF);
    unsigned long long* t2   = (unsigned long long*)(sm + T2_OFF);
    unsigned*           hist = (unsigned*)(sm + HIST_OFF);
    unsigned*           cur  = (unsigned*)(sm + CUR_OFF);
    unsigned*           wscr = (unsigned*)(sm + WSCR_OFF);
    unsigned long long* red  = (unsigned long long*)(sm + RED_OFF);

    const int c = blockIdx.x;
    const int t = threadIdx.x;
    const float* __restrict__ pcol = g_pT + (size_t)c * NR;
    const float* __restrict__ tcg  = g_tT + (size_t)c * NR;

    for (int i = t; i < NB; i += BT) hist[i] = 0;
    float pv[IPT];
#pragma unroll
    for (int j = 0; j < IPT; j++) {
        pv[j] = pcol[t + j * BT];
        tcol[t + j * BT] = tcg[t + j * BT];
    }
    __syncthreads();

    // ---- phase 1: histogram ----
    unsigned long long rec[IPT];
    int bn[IPT];
#pragma unroll
    for (int j = 0; j < IPT; j++) {
        unsigned row = (unsigned)(t + j * BT);
        bn[j]  = binf(pv[j]);
        rec[j] = ((unsigned long long)f2u(pv[j]) << 13) | row;
        atomicAdd(&hist[bn[j]], 1u);
    }
    __syncthreads();
    scan_bins8(hist, cur, wscr, t);
    __syncthreads();
#pragma unroll
    for (int j = 0; j < IPT; j++) {
        unsigned s = atomicAdd(&cur[bn[j]], 1u);
        g[s] = rec[j];
    }
    __syncthreads();
    // pack ranges: hist[b] = start<<16 | end
    for (int i = t; i < NB; i += BT) {
        unsigned e = cur[i], h = hist[i];
        hist[i] = ((e - h) << 16) | e;
    }
    __syncthreads();

    // ---- phase 1 rank + select (grouped slot order; skip bins wholly below median) ----
    const ulonglong2* gv = (const ulonglong2*)g;
#pragma unroll
    for (int jj = 0; jj < IPT / 2; jj++) {
        ulonglong2 pair = gv[t * (IPT / 2) + jj];
#pragma unroll
        for (int h = 0; h < 2; h++) {
            unsigned long long r = h ? pair.y : pair.x;
            unsigned key = (unsigned)(r >> 13);
            int b = binf(u2f(key));
            unsigned pk  = hist[b];
            unsigned end = pk & 0xffffu;
            if (end > KSEL) {
                unsigned rk = pk >> 16;          // start
                for (unsigned q = pk >> 16; q < end; q++)
                    rk += (g[q] < r);
                if (rk >= KSEL) {
                    unsigned pr  = rk - KSEL;
                    unsigned row = (unsigned)(r & 8191u);
                    float tv = tcol[row];
                    t2[pr] = ((unsigned long long)f2u(tv) << 13) | pr;
                }
            }
        }
    }
    __syncthreads();

    // ---- phase 2: histogram target keys of selected ----
    for (int i = t; i < NB; i += BT) hist[i] = 0;
    __syncthreads();
    unsigned long long r2[IPT2];
    int bn2[IPT2];
    {
        const ulonglong2* t2v = (const ulonglong2*)t2;
#pragma unroll
        for (int jj = 0; jj < IPT2 / 2; jj++) {
            ulonglong2 pair = t2v[t * (IPT2 / 2) + jj];
            r2[2 * jj]     = pair.x;
            r2[2 * jj + 1] = pair.y;
        }
    }
#pragma unroll
    for (int j = 0; j < IPT2; j++) {
        bn2[j] = binf(u2f((unsigned)(r2[j] >> 13)));
        atomicAdd(&hist[bn2[j]], 1u);
    }
    __syncthreads();
    scan_bins8(hist, cur, wscr, t);
    __syncthreads();
#pragma unroll
    for (int j = 0; j < IPT2; j++) {
        unsigned s = atomicAdd(&cur[bn2[j]], 1u);
        g[s] = r2[j];
    }
    __syncthreads();
    for (int i = t; i < NB; i += BT) {
        unsigned e = cur[i], h = hist[i];
        hist[i] = ((e - h) << 16) | e;
    }
    __syncthreads();

    // ---- phase 2 rank + dot ----
    unsigned long long acc = 0;
#pragma unroll
    for (int jj = 0; jj < IPT2 / 2; jj++) {
        ulonglong2 pair = gv[t * (IPT2 / 2) + jj];
#pragma unroll
        for (int h = 0; h < 2; h++) {
            unsigned long long r = h ? pair.y : pair.x;
            unsigned key = (unsigned)(r >> 13);
            int b = binf(u2f(key));
            unsigned pk  = hist[b];
            unsigned end = pk & 0xffffu;
            unsigned rk  = pk >> 16;
            for (unsigned q = pk >> 16; q < end; q++)
                rk += (g[q] < r);
            acc += (unsigned long long)(r & 8191u) * (unsigned long long)rk;
        }
    }

    // ---- reduce S ----
#pragma unroll
    for (int d = 16; d > 0; d >>= 1)
        acc += __shfl_down_sync(0xffffffffu, acc, d);
    if ((t & 31) == 0) red[t >> 5] = acc;
    __syncthreads();
    if (t < 32) {
        unsigned long long v = red[t];
#pragma unroll
        for (int d = 16; d > 0; d >>= 1)
            v += __shfl_down_sync(0xffffffffu, v, d);
        if (t == 0) {
            double S   = (double)v;
            double k   = (double)KSEL;
            double mu  = (k - 1.0) * 0.5;
            double cov = S / k - mu * mu;
            double var = k * (k + 1.0) / 12.0;
            out[c] = (float)(cov / (var + 1e-8));
        }
    }
}

extern "C" void kernel_launch(void* const* d_in, const int* in_sizes, int n_in,
                              void* d_out, int out_size)
{
    const float* preds   = (const float*)d_in[0];
    const float* targets = (const float*)d_in[1];
    float*       out     = (float*)d_out;

    dim3 tb(16, 16, 1);
    dim3 tg(NC / 64, NR / 64, 2);
    transpose_k<<<tg, tb>>>(preds, targets);

    cudaFuncSetAttribute(rank_ic_kernel,
                         cudaFuncAttributeMaxDynamicSharedMemorySize, SMEM_TOTAL);
    rank_ic_kernel<<<NC, BT, SMEM_TOTAL>>>(out);
}

// round 15
// speedup vs baseline: 3.7069x; 1.3527x over previous
#include <cuda_runtime.h>

// LongRankIC via exact binned ranking (no sort).
// ic = (S/k - mu^2)/(k(k+1)/12 + eps), S = sum over selected of p_rank*t_rank.
// Selection = ascending pred-rank in [k,2k). Ranks exact via 8192-bin
// histogram + within-bin count of strictly-smaller (key, row) pairs.
// hist[b] packs start<<16|cursor; scatter atomicAdd increments cursor in place.
// 2 CTAs/SM: 98.7 KB smem, target values read via __ldg (L1-resident column).

#define NR 8192
#define NC 4096
#define KSEL 4096
#define BT 1024
#define NB 8192
#define IPT 8
#define IPT2 4

__device__ float g_pT[(size_t)NC * NR];
__device__ float g_tT[(size_t)NC * NR];

__device__ __forceinline__ unsigned f2u(float f) {
    unsigned u = __float_as_uint(f);
    return u ^ ((unsigned)((int)u >> 31) | 0x80000000u);
}
__device__ __forceinline__ float u2f(unsigned u) {
    unsigned v = (u & 0x80000000u) ? (u ^ 0x80000000u) : ~u;
    return __uint_as_float(v);
}
// monotone (non-strict) in x; NB bins over ~[-4,4)
__device__ __forceinline__ int binf(float x) {
    int b = (int)fmaf(x, 1024.0f, 4096.0f);
    return min(max(b, 0), NB - 1);
}

// ---------------- transpose: 64x64 tiles, float4 (at LTS cap) ----------------
__global__ void transpose_k(const float* __restrict__ preds,
                            const float* __restrict__ targets)
{
    __shared__ float tile[64][65];
    const float* src = blockIdx.z ? targets : preds;
    float* dst       = blockIdx.z ? g_tT : g_pT;
    int c0 = blockIdx.x * 64, r0 = blockIdx.y * 64;
    int tx = threadIdx.x, ty = threadIdx.y;   // (16,16)
#pragma unroll
    for (int k = 0; k < 4; k++) {
        int row = r0 + ty + 16 * k;
        float4 f = *(const float4*)&src[(size_t)row * NC + c0 + 4 * tx];
        tile[ty + 16 * k][4 * tx + 0] = f.x;
        tile[ty + 16 * k][4 * tx + 1] = f.y;
        tile[ty + 16 * k][4 * tx + 2] = f.z;
        tile[ty + 16 * k][4 * tx + 3] = f.w;
    }
    __syncthreads();
#pragma unroll
    for (int k = 0; k < 4; k++) {
        int j = ty + 16 * k;
        float4 o;
        o.x = tile[4 * tx + 0][j];
        o.y = tile[4 * tx + 1][j];
        o.z = tile[4 * tx + 2][j];
        o.w = tile[4 * tx + 3][j];
        *(float4*)&dst[(size_t)(c0 + j) * NR + r0 + 4 * tx] = o;
    }
}

// ---------------- smem layout (98688 B -> 2 CTAs/SM) ----------------
#define GK_OFF   0          // u32[NR]    32768   keys, grouped by bin
#define GR_OFF   32768      // u16[NR]    16384   rows/p_ranks, grouped
#define T2K_OFF  49152      // u32[KSEL]  16384   selected t-keys by p_rank
#define HIST_OFF 65536      // u32[NB]    32768   counts -> start<<16|cursor
#define WSCR_OFF 98304      // u32[32]    128
#define RED_OFF  98432      // u64[32]    256
#define SMEM_TOTAL 98688

// scan counts in hist[0..NB) -> write packed start<<16|start in place
__device__ __forceinline__ void scan_bins8(unsigned* hist, unsigned* wscr, int t)
{
    uint4 a = *(uint4*)&hist[8 * t];
    uint4 b = *(uint4*)&hist[8 * t + 4];
    unsigned pre[8];
    unsigned e = 0;
    pre[0] = e; e += a.x; pre[1] = e; e += a.y;
    pre[2] = e; e += a.z; pre[3] = e; e += a.w;
    pre[4] = e; e += b.x; pre[5] = e; e += b.y;
    pre[6] = e; e += b.z; pre[7] = e; e += b.w;
    unsigned inc = e;
#pragma unroll
    for (int d = 1; d < 32; d <<= 1) {
        unsigned n = __shfl_up_sync(0xffffffffu, inc, d);
        if ((t & 31) >= d) inc += n;
    }
    if ((t & 31) == 31) wscr[t >> 5] = inc;
    __syncthreads();
    if (t < 32) {
        unsigned w = wscr[t];
        unsigned wi = w;
#pragma unroll
        for (int d = 1; d < 32; d <<= 1) {
            unsigned n = __shfl_up_sync(0xffffffffu, wi, d);
            if (t >= d) wi += n;
        }
        wscr[t] = wi - w;
    }
    __syncthreads();
    unsigned base = wscr[t >> 5] + (inc - e);
    unsigned s0 = base + pre[0], s1 = base + pre[1], s2 = base + pre[2], s3 = base + pre[3];
    unsigned s4 = base + pre[4], s5 = base + pre[5], s6 = base + pre[6], s7 = base + pre[7];
    *(uint4*)&hist[8 * t]     = make_uint4((s0<<16)|s0, (s1<<16)|s1, (s2<<16)|s2, (s3<<16)|s3);
    *(uint4*)&hist[8 * t + 4] = make_uint4((s4<<16)|s4, (s5<<16)|s5, (s6<<16)|s6, (s7<<16)|s7);
}

__global__ void __launch_bounds__(BT, 2)
rank_ic_kernel(float* __restrict__ out)
{
    extern __shared__ char sm[];
    unsigned*           gk   = (unsigned*)(sm + GK_OFF);
    unsigned short*     gr   = (unsigned short*)(sm + GR_OFF);
    unsigned*           t2k  = (unsigned*)(sm + T2K_OFF);
    unsigned*           hist = (unsigned*)(sm + HIST_OFF);
    unsigned*           wscr = (unsigned*)(sm + WSCR_OFF);
    unsigned long long* red  = (unsigned long long*)(sm + RED_OFF);

    const int c = blockIdx.x;
    const int t = threadIdx.x;
    const float* __restrict__ pcol = g_pT + (size_t)c * NR;
    const float* __restrict__ tcg  = g_tT + (size_t)c * NR;

    // ---- zero hist (uint4) ----
    uint4 z = make_uint4(0, 0, 0, 0);
    *(uint4*)&hist[8 * t]     = z;
    *(uint4*)&hist[8 * t + 4] = z;
    __syncthreads();

    // ---- phase 1: load + histogram (keys kept in regs; bins recomputed) ----
    unsigned kv[IPT];
#pragma unroll
    for (int j = 0; j < IPT; j++) {
        float x = pcol[t + j * BT];
        kv[j] = f2u(x);
        atomicAdd(&hist[binf(x)], 1u);
    }
    __syncthreads();
    scan_bins8(hist, wscr, t);
    __syncthreads();
    // scatter: cursor lives in low 16 bits of packed hist
#pragma unroll
    for (int j = 0; j < IPT; j++) {
        unsigned s = atomicAdd(&hist[binf(u2f(kv[j]))], 1u) & 0xffffu;
        gk[s] = kv[j];
        gr[s] = (unsigned short)(t + j * BT);
    }
    __syncthreads();
    // hist[b] = start<<16 | end

    // ---- phase 1 rank + select (cyclic; skip bins wholly below median) ----
#pragma unroll
    for (int j = 0; j < IPT; j++) {
        int s = t + j * BT;
        unsigned key = gk[s];
        int b = binf(u2f(key));
        unsigned pk  = hist[b];
        unsigned end = pk & 0xffffu;
        if (end > KSEL) {
            unsigned row = gr[s];
            unsigned start = pk >> 16;
            unsigned rk = start;
            for (unsigned q = start; q < end; q++) {
                unsigned kq = gk[q];
                if (kq < key) rk++;
                else if (kq == key && gr[q] < row) rk++;
            }
            if (rk >= KSEL)
                t2k[rk - KSEL] = f2u(__ldg(tcg + row));   // index == p_rank
        }
    }
    __syncthreads();

    // ---- phase 2: histogram selected t-keys ----
    *(uint4*)&hist[8 * t]     = z;
    *(uint4*)&hist[8 * t + 4] = z;
    __syncthreads();
    unsigned k2[IPT2];
#pragma unroll
    for (int j = 0; j < IPT2; j++) {
        k2[j] = t2k[t + j * BT];
        atomicAdd(&hist[binf(u2f(k2[j]))], 1u);
    }
    __syncthreads();
    scan_bins8(hist, wscr, t);
    __syncthreads();
#pragma unroll
    for (int j = 0; j < IPT2; j++) {
        unsigned s = atomicAdd(&hist[binf(u2f(k2[j]))], 1u) & 0xffffu;
        gk[s] = k2[j];
        gr[s] = (unsigned short)(t + j * BT);   // p_rank
    }
    __syncthreads();

    // ---- phase 2 rank + dot (cyclic) ----
    unsigned long long acc = 0;
#pragma unroll
    for (int j = 0; j < IPT2; j++) {
        int s = t + j * BT;
        unsigned key = gk[s];
        unsigned pr  = gr[s];
        int b = binf(u2f(key));
        unsigned pk    = hist[b];
        unsigned end   = pk & 0xffffu;
        unsigned start = pk >> 16;
        unsigned rk = start;
        for (unsigned q = start; q < end; q++) {
            unsigned kq = gk[q];
            if (kq < key) rk++;
            else if (kq == key && gr[q] < pr) rk++;
        }
        acc += (unsigned long long)pr * (unsigned long long)rk;
    }

    // ---- reduce S ----
#pragma unroll
    for (int d = 16; d > 0; d >>= 1)
        acc += __shfl_down_sync(0xffffffffu, acc, d);
    if ((t & 31) == 0) red[t >> 5] = acc;
    __syncthreads();
    if (t < 32) {
        unsigned long long v = red[t];
#pragma unroll
        for (int d = 16; d > 0; d >>= 1)
            v += __shfl_down_sync(0xffffffffu, v, d);
        if (t == 0) {
            double S   = (double)v;
            double k   = (double)KSEL;
            double mu  = (k - 1.0) * 0.5;
            double cov = S / k - mu * mu;
            double var = k * (k + 1.0) / 12.0;
            out[c] = (float)(cov / (var + 1e-8));
        }
    }
}

extern "C" void kernel_launch(void* const* d_in, const int* in_sizes, int n_in,
                              void* d_out, int out_size)
{
    const float* preds   = (const float*)d_in[0];
    const float* targets = (const float*)d_in[1];
    float*       out     = (float*)d_out;

    dim3 tb(16, 16, 1);
    dim3 tg(NC / 64, NR / 64, 2);
    transpose_k<<<tg, tb>>>(preds, targets);

    cudaFuncSetAttribute(rank_ic_kernel,
                         cudaFuncAttributeMaxDynamicSharedMemorySize, SMEM_TOTAL);
    rank_ic_kernel<<<NC, BT, SMEM_TOTAL>>>(out);
}